// round 1
// baseline (speedup 1.0000x reference)
#include <cuda_runtime.h>
#include <cuda_bf16.h>
#include <math_constants.h>

// Problem constants
#define BATCH 2
#define SEQ   2048
#define DIM   512
#define HEADS 8
#define DHEAD 64
#define INNER 512
#define MROWS (BATCH * SEQ)       // 4096
#define SCALE 0.125f              // 64^-0.5

// ---------------- scratch (no allocations allowed) ----------------
__device__ float g_Q[BATCH * HEADS * SEQ * DHEAD];   // [b,h,n,d]
__device__ float g_K[BATCH * HEADS * SEQ * DHEAD];
__device__ float g_V[BATCH * HEADS * SEQ * DHEAD];
__device__ float g_AO[MROWS * INNER];                // [b,n, h*64+d]

// ---------------- generic tiled GEMM: C = A[M,512] @ W[512,Nout] ----------------
// MODE 0: kv projection -> scatter to g_K (cols 0..511) / g_V (cols 512..1023)
// MODE 1: q projection  -> scatter to g_Q
// MODE 2: out projection -> C0[m*512+c] = acc + bias[c]
#define BM 128
#define BN 128
#define BK 16

template <int MODE>
__global__ void __launch_bounds__(256)
gemm_kernel(const float* __restrict__ A,
            const float* __restrict__ W,
            float* __restrict__ C0,
            const float* __restrict__ bias,
            int Nout)
{
    __shared__ float As[BK][BM + 4];   // A transposed: As[k][m]
    __shared__ float Bs[BK][BN + 4];   // Bs[k][n]

    const int K  = DIM;
    const int m0 = blockIdx.y * BM;
    const int n0 = blockIdx.x * BN;
    const int tid = threadIdx.x;
    const int tx = tid & 15;
    const int ty = tid >> 4;

    // load index mapping
    const int ar = tid >> 2;            // 0..63
    const int ac = (tid & 3) * 4;       // 0,4,8,12
    const int br = tid >> 5;            // 0..7
    const int bc = (tid & 31) * 4;      // 0..124

    float acc[8][8];
#pragma unroll
    for (int i = 0; i < 8; i++)
#pragma unroll
        for (int j = 0; j < 8; j++) acc[i][j] = 0.f;

    for (int k0 = 0; k0 < K; k0 += BK) {
#pragma unroll
        for (int rr = 0; rr < 2; rr++) {
            float4 v = *(const float4*)&A[(size_t)(m0 + ar + rr * 64) * K + k0 + ac];
            As[ac + 0][ar + rr * 64] = v.x;
            As[ac + 1][ar + rr * 64] = v.y;
            As[ac + 2][ar + rr * 64] = v.z;
            As[ac + 3][ar + rr * 64] = v.w;
        }
#pragma unroll
        for (int rr = 0; rr < 2; rr++) {
            float4 v = *(const float4*)&W[(size_t)(k0 + br + rr * 8) * Nout + n0 + bc];
            *(float4*)&Bs[br + rr * 8][bc] = v;
        }
        __syncthreads();

#pragma unroll
        for (int kk = 0; kk < BK; kk++) {
            float a[8], b[8];
            *(float4*)&a[0] = *(const float4*)&As[kk][ty * 8];
            *(float4*)&a[4] = *(const float4*)&As[kk][ty * 8 + 4];
            *(float4*)&b[0] = *(const float4*)&Bs[kk][tx * 8];
            *(float4*)&b[4] = *(const float4*)&Bs[kk][tx * 8 + 4];
#pragma unroll
            for (int i = 0; i < 8; i++)
#pragma unroll
                for (int j = 0; j < 8; j++)
                    acc[i][j] += a[i] * b[j];
        }
        __syncthreads();
    }

    // epilogue
#pragma unroll
    for (int i = 0; i < 8; i++) {
        const int m = m0 + ty * 8 + i;
        const int b = m >> 11;        // /2048
        const int n = m & 2047;
#pragma unroll
        for (int j = 0; j < 8; j++) {
            const int c = n0 + tx * 8 + j;
            const float v = acc[i][j];
            if (MODE == 0) {
                if (c < INNER) {
                    const int h = c >> 6, d = c & 63;
                    g_K[(((size_t)(b * HEADS + h)) * SEQ + n) * DHEAD + d] = v;
                } else {
                    const int c2 = c - INNER;
                    const int h = c2 >> 6, d = c2 & 63;
                    g_V[(((size_t)(b * HEADS + h)) * SEQ + n) * DHEAD + d] = v;
                }
            } else if (MODE == 1) {
                const int h = c >> 6, d = c & 63;
                g_Q[(((size_t)(b * HEADS + h)) * SEQ + n) * DHEAD + d] = v;
            } else {
                C0[(size_t)m * INNER + c] = v + bias[c];
            }
        }
    }
}

// ---------------- flash attention ----------------
// grid: (SEQ/AQ, B*H); 256 threads (16x16). AQ=64 query rows, AK=128 key rows/tile.
#define AQ 64
#define AK 128
#define QS_STRIDE 68     // [d][row]
#define KS_STRIDE 132    // [d][key]
#define VS_STRIDE 68     // [key][d]
#define PS_STRIDE 68     // [key][row]
#define QS_SZ (64 * QS_STRIDE)
#define KS_SZ (64 * KS_STRIDE)
#define VS_SZ (AK * VS_STRIDE)
#define PS_SZ (AK * PS_STRIDE)
#define ATTN_SMEM ((QS_SZ + KS_SZ + VS_SZ + PS_SZ) * sizeof(float))

__global__ void __launch_bounds__(256)
attn_kernel(void)
{
    extern __shared__ float sm[];
    float* Qs = sm;                 // [64 d][68]: Qs[d*68 + row]
    float* Ks = Qs + QS_SZ;         // [64 d][132]: Ks[d*132 + key]
    float* Vs = Ks + KS_SZ;         // [128 key][68]: Vs[key*68 + d]
    float* Ps = Vs + VS_SZ;         // [128 key][68]: Ps[key*68 + row]

    const int bh = blockIdx.y;                     // 0..15
    const int q0 = blockIdx.x * AQ;
    const float* Qg = g_Q + (size_t)bh * SEQ * DHEAD;
    const float* Kg = g_K + (size_t)bh * SEQ * DHEAD;
    const float* Vg = g_V + (size_t)bh * SEQ * DHEAD;

    const int tid = threadIdx.x;
    const int tx = tid & 15;        // key/col group
    const int ty = tid >> 4;        // row group

    // --- load Q tile (64 rows x 64 d), transposed into Qs[d][row] ---
    {
        const int row = tid >> 2;             // 0..63
        const int d0  = (tid & 3) * 16;       // 0,16,32,48
#pragma unroll
        for (int i = 0; i < 4; i++) {
            float4 v = *(const float4*)&Qg[(size_t)(q0 + row) * DHEAD + d0 + i * 4];
            Qs[(d0 + i * 4 + 0) * QS_STRIDE + row] = v.x;
            Qs[(d0 + i * 4 + 1) * QS_STRIDE + row] = v.y;
            Qs[(d0 + i * 4 + 2) * QS_STRIDE + row] = v.z;
            Qs[(d0 + i * 4 + 3) * QS_STRIDE + row] = v.w;
        }
    }

    float mrow[4], lrow[4], oacc[4][4];
#pragma unroll
    for (int i = 0; i < 4; i++) {
        mrow[i] = -CUDART_INF_F;
        lrow[i] = 0.f;
#pragma unroll
        for (int j = 0; j < 4; j++) oacc[i][j] = 0.f;
    }

    const int kload = tid >> 1;               // 0..127
    const int dload = (tid & 1) * 32;         // 0,32

    for (int kv0 = 0; kv0 < SEQ; kv0 += AK) {
        // --- load K tile transposed, V tile direct ---
#pragma unroll
        for (int i = 0; i < 8; i++) {
            float4 v = *(const float4*)&Kg[(size_t)(kv0 + kload) * DHEAD + dload + i * 4];
            Ks[(dload + i * 4 + 0) * KS_STRIDE + kload] = v.x;
            Ks[(dload + i * 4 + 1) * KS_STRIDE + kload] = v.y;
            Ks[(dload + i * 4 + 2) * KS_STRIDE + kload] = v.z;
            Ks[(dload + i * 4 + 3) * KS_STRIDE + kload] = v.w;
        }
#pragma unroll
        for (int i = 0; i < 8; i++) {
            float4 v = *(const float4*)&Vg[(size_t)(kv0 + kload) * DHEAD + dload + i * 4];
            *(float4*)&Vs[kload * VS_STRIDE + dload + i * 4] = v;
        }
        __syncthreads();

        // --- S = Q @ K^T (per thread: 4 rows x 8 keys) ---
        float s[4][8];
#pragma unroll
        for (int i = 0; i < 4; i++)
#pragma unroll
            for (int j = 0; j < 8; j++) s[i][j] = 0.f;

#pragma unroll 4
        for (int d = 0; d < DHEAD; d++) {
            float a[4], b[8];
            *(float4*)&a[0] = *(const float4*)&Qs[d * QS_STRIDE + ty * 4];
            *(float4*)&b[0] = *(const float4*)&Ks[d * KS_STRIDE + tx * 8];
            *(float4*)&b[4] = *(const float4*)&Ks[d * KS_STRIDE + tx * 8 + 4];
#pragma unroll
            for (int i = 0; i < 4; i++)
#pragma unroll
                for (int j = 0; j < 8; j++)
                    s[i][j] += a[i] * b[j];
        }

        // --- online softmax (reduce across 8 local cols + 16 tx lanes) ---
#pragma unroll
        for (int i = 0; i < 4; i++) {
            float mx = s[i][0] * SCALE;
#pragma unroll
            for (int j = 1; j < 8; j++) mx = fmaxf(mx, s[i][j] * SCALE);
#pragma unroll
            for (int off = 8; off > 0; off >>= 1)
                mx = fmaxf(mx, __shfl_xor_sync(0xffffffffu, mx, off));

            const float mnew = fmaxf(mrow[i], mx);
            const float alpha = __expf(mrow[i] - mnew);
            mrow[i] = mnew;

            float rsum = 0.f;
#pragma unroll
            for (int j = 0; j < 8; j++) {
                const float p = __expf(s[i][j] * SCALE - mnew);
                s[i][j] = p;
                rsum += p;
            }
#pragma unroll
            for (int off = 8; off > 0; off >>= 1)
                rsum += __shfl_xor_sync(0xffffffffu, rsum, off);

            lrow[i] = lrow[i] * alpha + rsum;
#pragma unroll
            for (int j = 0; j < 4; j++) oacc[i][j] *= alpha;
        }

        // --- stage P transposed: Ps[key][row] ---
#pragma unroll
        for (int j = 0; j < 8; j++)
#pragma unroll
            for (int i = 0; i < 4; i++)
                Ps[(tx * 8 + j) * PS_STRIDE + ty * 4 + i] = s[i][j];
        __syncthreads();

        // --- O += P @ V (per thread: 4 rows x 4 d-cols) ---
#pragma unroll 4
        for (int k = 0; k < AK; k++) {
            float a[4], b[4];
            *(float4*)&a[0] = *(const float4*)&Ps[k * PS_STRIDE + ty * 4];
            *(float4*)&b[0] = *(const float4*)&Vs[k * VS_STRIDE + tx * 4];
#pragma unroll
            for (int i = 0; i < 4; i++)
#pragma unroll
                for (int j = 0; j < 4; j++)
                    oacc[i][j] += a[i] * b[j];
        }
        __syncthreads();   // before next tile overwrites Ks/Vs/Ps
    }

    // --- finalize: AO[b][n][h*64+d] ---
    const int b = bh >> 3;
    const int h = bh & 7;
#pragma unroll
    for (int i = 0; i < 4; i++) {
        const int n = q0 + ty * 4 + i;
        const float inv = 1.f / lrow[i];
#pragma unroll
        for (int j = 0; j < 4; j++) {
            const int d = tx * 4 + j;
            g_AO[((size_t)(b * SEQ + n)) * INNER + h * DHEAD + d] = oacc[i][j] * inv;
        }
    }
}

// ---------------- launch ----------------
extern "C" void kernel_launch(void* const* d_in, const int* in_sizes, int n_in,
                              void* d_out, int out_size)
{
    const float* x1    = (const float*)d_in[0];   // [2,2048,512]
    const float* x2    = (const float*)d_in[1];   // [2,2048,512]
    const float* W_qk  = (const float*)d_in[2];   // [512,1024]
    const float* W_v   = (const float*)d_in[3];   // [512,512]
    const float* W_out = (const float*)d_in[4];   // [512,512]
    const float* b_out = (const float*)d_in[5];   // [512]
    float* out = (float*)d_out;

    (void)in_sizes; (void)n_in; (void)out_size;

    cudaFuncSetAttribute(attn_kernel, cudaFuncAttributeMaxDynamicSharedMemorySize,
                         (int)ATTN_SMEM);

    float* gAO;
    cudaGetSymbolAddress((void**)&gAO, g_AO);

    // 1) kv = x1 @ W_qk  -> g_K, g_V
    gemm_kernel<0><<<dim3(2 * INNER / BN, MROWS / BM), 256>>>(x1, W_qk, nullptr, nullptr, 2 * INNER);
    // 2) q = x2 @ W_v    -> g_Q
    gemm_kernel<1><<<dim3(INNER / BN, MROWS / BM), 256>>>(x2, W_v, nullptr, nullptr, INNER);
    // 3) attention -> g_AO
    attn_kernel<<<dim3(SEQ / AQ, BATCH * HEADS), 256, ATTN_SMEM>>>();
    // 4) out = g_AO @ W_out + b_out
    gemm_kernel<2><<<dim3(DIM / BN, MROWS / BM), 256>>>(gAO, W_out, out, b_out, DIM);
}

// round 2
// speedup vs baseline: 3.9002x; 3.9002x over previous
#include <cuda_runtime.h>
#include <cstdint>

// Problem constants
#define BATCH 2
#define SEQ   2048
#define DIM   512
#define HEADS 8
#define DHEAD 64
#define INNER 512
#define MROWS (BATCH * SEQ)       // 4096
#define SCALE 0.125f

// ---------------- scratch ----------------
__device__ float g_Q[BATCH * HEADS * SEQ * DHEAD];   // [b,h,n,d]
__device__ float g_K[BATCH * HEADS * SEQ * DHEAD];
__device__ float g_V[BATCH * HEADS * SEQ * DHEAD];
__device__ float g_AO[MROWS * INNER];                // [b,n, h*64+d]

// ---------------- tf32 helpers ----------------
__device__ __forceinline__ uint32_t f2tf(float x) {
    uint32_t r;
    asm("cvt.rna.tf32.f32 %0, %1;" : "=r"(r) : "f"(x));
    return r;
}

// D += A*B, m16n8k8 tf32. c[4] fp32, a[4], b[2] tf32-in-b32.
__device__ __forceinline__ void mma8(float* c, const uint32_t* a, const uint32_t* b) {
    asm volatile(
        "mma.sync.aligned.m16n8k8.row.col.f32.tf32.tf32.f32 "
        "{%0,%1,%2,%3},{%4,%5,%6,%7},{%8,%9},{%0,%1,%2,%3};"
        : "+f"(c[0]), "+f"(c[1]), "+f"(c[2]), "+f"(c[3])
        : "r"(a[0]), "r"(a[1]), "r"(a[2]), "r"(a[3]), "r"(b[0]), "r"(b[1]));
}

// ---------------- GEMM: C = A[M,512] @ W[512,Nout] ----------------
// MODE 0: kv proj -> g_K (cols<512) / g_V ; MODE 1: q proj -> g_Q ; MODE 2: C0 = acc + bias
#define BM 128
#define BN 64
#define BK 32
#define AS_STR 36   // As[m][k], bank = (4g + c) -> conflict-free frag reads
#define BS_STR 72   // Bs[k][n], bank = (8c + g) -> conflict-free frag reads

template <int MODE>
__global__ void __launch_bounds__(256)
gemm_kernel(const float* __restrict__ A,
            const float* __restrict__ W,
            float* __restrict__ C0,
            const float* __restrict__ bias,
            int Nout)
{
    __shared__ uint32_t As[BM * AS_STR];
    __shared__ uint32_t Bs[BK * BS_STR];

    const int m0 = blockIdx.y * BM;
    const int n0 = blockIdx.x * BN;
    const int tid  = threadIdx.x;
    const int warp = tid >> 5;
    const int lane = tid & 31;
    const int wm = warp >> 2;       // 0..1 : 64 rows each
    const int wn = warp & 3;        // 0..3 : 16 cols each
    const int g  = lane >> 2;       // groupID
    const int c  = lane & 3;        // thread-in-group

    float acc[4][2][4];             // [mtile][ntile][reg]
#pragma unroll
    for (int i = 0; i < 4; i++)
#pragma unroll
        for (int j = 0; j < 2; j++)
#pragma unroll
            for (int r = 0; r < 4; r++) acc[i][j][r] = 0.f;

    for (int k0 = 0; k0 < DIM; k0 += BK) {
        // --- stage A tile [128 x 32] (tf32) ---
#pragma unroll
        for (int r = 0; r < 4; r++) {
            const int m = r * 32 + (tid >> 3);
            const int k = (tid & 7) * 4;
            float4 v = *(const float4*)&A[(size_t)(m0 + m) * DIM + k0 + k];
            uint4 t = make_uint4(f2tf(v.x), f2tf(v.y), f2tf(v.z), f2tf(v.w));
            *(uint4*)&As[m * AS_STR + k] = t;
        }
        // --- stage B tile [32 x 64] (tf32) ---
#pragma unroll
        for (int r = 0; r < 2; r++) {
            const int k = r * 16 + (tid >> 4);
            const int n = (tid & 15) * 4;
            float4 v = *(const float4*)&W[(size_t)(k0 + k) * Nout + n0 + n];
            uint4 t = make_uint4(f2tf(v.x), f2tf(v.y), f2tf(v.z), f2tf(v.w));
            *(uint4*)&Bs[k * BS_STR + n] = t;
        }
        __syncthreads();

#pragma unroll
        for (int kk = 0; kk < 4; kk++) {
            uint32_t bf[2][2];
#pragma unroll
            for (int nt = 0; nt < 2; nt++) {
                const int n = wn * 16 + nt * 8 + g;
                bf[nt][0] = Bs[(kk * 8 + c) * BS_STR + n];
                bf[nt][1] = Bs[(kk * 8 + c + 4) * BS_STR + n];
            }
#pragma unroll
            for (int mt = 0; mt < 4; mt++) {
                const int m = wm * 64 + mt * 16 + g;
                uint32_t af[4];
                af[0] = As[m * AS_STR + kk * 8 + c];
                af[1] = As[(m + 8) * AS_STR + kk * 8 + c];
                af[2] = As[m * AS_STR + kk * 8 + c + 4];
                af[3] = As[(m + 8) * AS_STR + kk * 8 + c + 4];
                mma8(acc[mt][0], af, bf[0]);
                mma8(acc[mt][1], af, bf[1]);
            }
        }
        __syncthreads();
    }

    // --- epilogue: C frag (row g / g+8, cols 2c, 2c+1) ---
#pragma unroll
    for (int mt = 0; mt < 4; mt++) {
#pragma unroll
        for (int rr = 0; rr < 2; rr++) {
            const int m = m0 + wm * 64 + mt * 16 + g + rr * 8;
            const int b = m >> 11;
            const int nrow = m & 2047;
#pragma unroll
            for (int nt = 0; nt < 2; nt++) {
                const int col = n0 + wn * 16 + nt * 8 + 2 * c;
                float v0 = acc[mt][nt][rr * 2 + 0];
                float v1 = acc[mt][nt][rr * 2 + 1];
                if (MODE == 0) {
                    if (col < INNER) {
                        const int h = col >> 6, d = col & 63;
                        *(float2*)&g_K[(((size_t)(b * HEADS + h)) * SEQ + nrow) * DHEAD + d]
                            = make_float2(v0, v1);
                    } else {
                        const int c2 = col - INNER;
                        const int h = c2 >> 6, d = c2 & 63;
                        *(float2*)&g_V[(((size_t)(b * HEADS + h)) * SEQ + nrow) * DHEAD + d]
                            = make_float2(v0, v1);
                    }
                } else if (MODE == 1) {
                    const int h = col >> 6, d = col & 63;
                    *(float2*)&g_Q[(((size_t)(b * HEADS + h)) * SEQ + nrow) * DHEAD + d]
                        = make_float2(v0, v1);
                } else {
                    *(float2*)&C0[(size_t)m * INNER + col]
                        = make_float2(v0 + bias[col], v1 + bias[col + 1]);
                }
            }
        }
    }
}

// ---------------- flash attention (tf32 mma) ----------------
// CTA: 128 queries, 8 warps (16 rows each). Key tile KT=64.
#define KT 64
#define KS_STR 68        // Ks/Vs [key][d]: frag bank = 4g+c (K), 4c+g (V) -> CF
#define PS_STR 68        // Ps [q][key]: frag bank = 4g+c -> CF
#define KS_WORDS (KT * KS_STR)          // 4352
#define PS_WORDS (128 * PS_STR)         // 8704
#define ATTN_SMEM ((2 * KS_WORDS + PS_WORDS) * sizeof(uint32_t))  // 69632 B

__global__ void __launch_bounds__(256, 2)
attn_kernel(void)
{
    extern __shared__ uint32_t smw[];
    uint32_t* Ks = smw;                  // [64 key][68 d]
    uint32_t* Vs = Ks + KS_WORDS;        // [64 key][68 d]
    uint32_t* Ps = Vs + KS_WORDS;        // [128 q][68 key]

    const int bh = blockIdx.y;           // 0..15
    const int q0 = blockIdx.x * 128;
    const float* Qg = g_Q + (size_t)bh * SEQ * DHEAD;
    const float* Kg = g_K + (size_t)bh * SEQ * DHEAD;
    const float* Vg = g_V + (size_t)bh * SEQ * DHEAD;

    const int tid  = threadIdx.x;
    const int warp = tid >> 5;
    const int lane = tid & 31;
    const int g = lane >> 2;
    const int c = lane & 3;
    const int qr = q0 + warp * 16 + g;   // this thread's row (also +8)

    // --- Q fragments in registers (SCALE folded in, exact since 0.125 = 2^-3) ---
    uint32_t qa[8][4];
#pragma unroll
    for (int kk = 0; kk < 8; kk++) {
        const int d = kk * 8 + c;
        qa[kk][0] = f2tf(SCALE * Qg[(size_t)qr * DHEAD + d]);
        qa[kk][1] = f2tf(SCALE * Qg[(size_t)(qr + 8) * DHEAD + d]);
        qa[kk][2] = f2tf(SCALE * Qg[(size_t)qr * DHEAD + d + 4]);
        qa[kk][3] = f2tf(SCALE * Qg[(size_t)(qr + 8) * DHEAD + d + 4]);
    }

    const float NEG_INF = __int_as_float(0xff800000);
    float m0r = NEG_INF, m1r = NEG_INF, l0 = 0.f, l1 = 0.f;
    float oacc[8][4];
#pragma unroll
    for (int dt = 0; dt < 8; dt++)
#pragma unroll
        for (int r = 0; r < 4; r++) oacc[dt][r] = 0.f;

    for (int kv0 = 0; kv0 < SEQ; kv0 += KT) {
        // --- stage K,V tiles [64 x 64] as tf32 ---
#pragma unroll
        for (int r = 0; r < 4; r++) {
            const int key = r * 16 + (tid >> 4);
            const int d   = (tid & 15) * 4;
            float4 kv = *(const float4*)&Kg[(size_t)(kv0 + key) * DHEAD + d];
            *(uint4*)&Ks[key * KS_STR + d] =
                make_uint4(f2tf(kv.x), f2tf(kv.y), f2tf(kv.z), f2tf(kv.w));
            float4 vv = *(const float4*)&Vg[(size_t)(kv0 + key) * DHEAD + d];
            *(uint4*)&Vs[key * KS_STR + d] =
                make_uint4(f2tf(vv.x), f2tf(vv.y), f2tf(vv.z), f2tf(vv.w));
        }
        __syncthreads();

        // --- S = Q @ K^T : sacc[nt][reg], warp covers 16q x 64key ---
        float sacc[8][4];
#pragma unroll
        for (int nt = 0; nt < 8; nt++)
#pragma unroll
            for (int r = 0; r < 4; r++) sacc[nt][r] = 0.f;

#pragma unroll
        for (int kk = 0; kk < 8; kk++) {
#pragma unroll
            for (int nt = 0; nt < 8; nt++) {
                uint32_t bf[2];
                const int key = nt * 8 + g;
                bf[0] = Ks[key * KS_STR + kk * 8 + c];
                bf[1] = Ks[key * KS_STR + kk * 8 + c + 4];
                mma8(sacc[nt], qa[kk], bf);
            }
        }

        // --- online softmax for rows g and g+8 ---
        float mx0 = NEG_INF, mx1 = NEG_INF;
#pragma unroll
        for (int nt = 0; nt < 8; nt++) {
            mx0 = fmaxf(mx0, fmaxf(sacc[nt][0], sacc[nt][1]));
            mx1 = fmaxf(mx1, fmaxf(sacc[nt][2], sacc[nt][3]));
        }
        mx0 = fmaxf(mx0, __shfl_xor_sync(0xffffffffu, mx0, 1));
        mx0 = fmaxf(mx0, __shfl_xor_sync(0xffffffffu, mx0, 2));
        mx1 = fmaxf(mx1, __shfl_xor_sync(0xffffffffu, mx1, 1));
        mx1 = fmaxf(mx1, __shfl_xor_sync(0xffffffffu, mx1, 2));

        const float mn0 = fmaxf(m0r, mx0);
        const float mn1 = fmaxf(m1r, mx1);
        const float a0 = __expf(m0r - mn0);
        const float a1 = __expf(m1r - mn1);
        m0r = mn0; m1r = mn1;

        float rs0 = 0.f, rs1 = 0.f;
#pragma unroll
        for (int nt = 0; nt < 8; nt++) {
            float p0 = __expf(sacc[nt][0] - mn0);
            float p1 = __expf(sacc[nt][1] - mn0);
            float p2 = __expf(sacc[nt][2] - mn1);
            float p3 = __expf(sacc[nt][3] - mn1);
            sacc[nt][0] = p0; sacc[nt][1] = p1; sacc[nt][2] = p2; sacc[nt][3] = p3;
            rs0 += p0 + p1;
            rs1 += p2 + p3;
        }
        rs0 += __shfl_xor_sync(0xffffffffu, rs0, 1);
        rs0 += __shfl_xor_sync(0xffffffffu, rs0, 2);
        rs1 += __shfl_xor_sync(0xffffffffu, rs1, 1);
        rs1 += __shfl_xor_sync(0xffffffffu, rs1, 2);
        l0 = l0 * a0 + rs0;
        l1 = l1 * a1 + rs1;
#pragma unroll
        for (int dt = 0; dt < 8; dt++) {
            oacc[dt][0] *= a0; oacc[dt][1] *= a0;
            oacc[dt][2] *= a1; oacc[dt][3] *= a1;
        }

        // --- stage P (warp-private rows; no barrier needed before reading back) ---
        const int prow = warp * 16 + g;
#pragma unroll
        for (int nt = 0; nt < 8; nt++) {
            *(uint2*)&Ps[prow * PS_STR + nt * 8 + 2 * c] =
                make_uint2(f2tf(sacc[nt][0]), f2tf(sacc[nt][1]));
            *(uint2*)&Ps[(prow + 8) * PS_STR + nt * 8 + 2 * c] =
                make_uint2(f2tf(sacc[nt][2]), f2tf(sacc[nt][3]));
        }

        // --- O += P @ V ---
#pragma unroll
        for (int kk = 0; kk < 8; kk++) {
            uint32_t af[4];
            af[0] = Ps[prow * PS_STR + kk * 8 + c];
            af[1] = Ps[(prow + 8) * PS_STR + kk * 8 + c];
            af[2] = Ps[prow * PS_STR + kk * 8 + c + 4];
            af[3] = Ps[(prow + 8) * PS_STR + kk * 8 + c + 4];
#pragma unroll
            for (int dt = 0; dt < 8; dt++) {
                uint32_t bf[2];
                bf[0] = Vs[(kk * 8 + c) * KS_STR + dt * 8 + g];
                bf[1] = Vs[(kk * 8 + c + 4) * KS_STR + dt * 8 + g];
                mma8(oacc[dt], af, bf);
            }
        }
        __syncthreads();   // before next tile overwrites Ks/Vs
    }

    // --- epilogue: AO[b][n][h*64+d] ---
    const int b = bh >> 3;
    const int h = bh & 7;
    const float inv0 = 1.f / l0;
    const float inv1 = 1.f / l1;
#pragma unroll
    for (int dt = 0; dt < 8; dt++) {
        const int d = dt * 8 + 2 * c;
        *(float2*)&g_AO[((size_t)(b * SEQ + qr)) * INNER + h * DHEAD + d] =
            make_float2(oacc[dt][0] * inv0, oacc[dt][1] * inv0);
        *(float2*)&g_AO[((size_t)(b * SEQ + qr + 8)) * INNER + h * DHEAD + d] =
            make_float2(oacc[dt][2] * inv1, oacc[dt][3] * inv1);
    }
}

// ---------------- launch ----------------
extern "C" void kernel_launch(void* const* d_in, const int* in_sizes, int n_in,
                              void* d_out, int out_size)
{
    const float* x1    = (const float*)d_in[0];
    const float* x2    = (const float*)d_in[1];
    const float* W_qk  = (const float*)d_in[2];
    const float* W_v   = (const float*)d_in[3];
    const float* W_out = (const float*)d_in[4];
    const float* b_out = (const float*)d_in[5];
    float* out = (float*)d_out;
    (void)in_sizes; (void)n_in; (void)out_size;

    cudaFuncSetAttribute(attn_kernel, cudaFuncAttributeMaxDynamicSharedMemorySize,
                         (int)ATTN_SMEM);

    float* gAO;
    cudaGetSymbolAddress((void**)&gAO, g_AO);

    gemm_kernel<0><<<dim3(2 * INNER / BN, MROWS / BM), 256>>>(x1, W_qk, nullptr, nullptr, 2 * INNER);
    gemm_kernel<1><<<dim3(INNER / BN, MROWS / BM), 256>>>(x2, W_v, nullptr, nullptr, INNER);
    attn_kernel<<<dim3(SEQ / 128, BATCH * HEADS), 256, ATTN_SMEM>>>();
    gemm_kernel<2><<<dim3(DIM / BN, MROWS / BM), 256>>>(gAO, W_out, out, b_out, DIM);
}

// round 3
// speedup vs baseline: 5.0701x; 1.3000x over previous
#include <cuda_runtime.h>
#include <cstdint>

// Problem constants
#define BATCH 2
#define SEQ   2048
#define DIM   512
#define HEADS 8
#define DHEAD 64
#define INNER 512
#define MROWS (BATCH * SEQ)
#define SCALE 0.125f

// ---------------- scratch ----------------
__device__ float g_Q[BATCH * HEADS * SEQ * DHEAD];   // [b,h,n,d]
__device__ float g_K[BATCH * HEADS * SEQ * DHEAD];
__device__ float g_V[BATCH * HEADS * SEQ * DHEAD];
__device__ float g_AO[MROWS * INNER];                // [b,n, h*64+d]

// ---------------- helpers ----------------
__device__ __forceinline__ uint32_t f2tf(float x) {
    uint32_t r;
    asm("cvt.rna.tf32.f32 %0, %1;" : "=r"(r) : "f"(x));
    return r;
}
__device__ __forceinline__ float ex2(float x) {
    float y;
    asm("ex2.approx.f32 %0, %1;" : "=f"(y) : "f"(x));
    return y;
}
// D += A*B, m16n8k8 tf32. c[4] fp32, a[4], b[2].
__device__ __forceinline__ void mma8(float* c, const uint32_t* a, const uint32_t* b) {
    asm volatile(
        "mma.sync.aligned.m16n8k8.row.col.f32.tf32.tf32.f32 "
        "{%0,%1,%2,%3},{%4,%5,%6,%7},{%8,%9},{%0,%1,%2,%3};"
        : "+f"(c[0]), "+f"(c[1]), "+f"(c[2]), "+f"(c[3])
        : "r"(a[0]), "r"(a[1]), "r"(a[2]), "r"(a[3]), "r"(b[0]), "r"(b[1]));
}

// ---------------- GEMM: C = A[M,512] @ W[512,Nout] ----------------
// 128x128 CTA tile, 8 warps each 64m x 32n, register double-buffered staging.
#define BM 128
#define BN 128
#define BK 32
#define AS_STR 36    // As[m][k]: frag bank = 4g+c -> CF
#define BS_STR 136   // Bs[k][n]: frag bank = 8c+8nt+g -> CF

template <int MODE>
__global__ void __launch_bounds__(256)
gemm_kernel(const float* __restrict__ A,
            const float* __restrict__ W,
            float* __restrict__ C0,
            const float* __restrict__ bias,
            int Nout)
{
    __shared__ uint32_t As[BM * AS_STR];   // 18.4 KB
    __shared__ uint32_t Bs[BK * BS_STR];   // 17.4 KB

    const int m0 = blockIdx.y * BM;
    const int n0 = blockIdx.x * BN;
    const int tid  = threadIdx.x;
    const int warp = tid >> 5;
    const int lane = tid & 31;
    const int wm = warp >> 2;       // 0..1 : 64 rows
    const int wn = warp & 3;        // 0..3 : 32 cols
    const int g  = lane >> 2;
    const int c  = lane & 3;

    const int am = tid >> 3;            // 0..31 (+32*r)
    const int ak = (tid & 7) * 4;
    const int bk = tid >> 5;            // 0..7 (+8*r)
    const int bn = (tid & 31) * 4;

    float4 pa[4], pb[4];
#pragma unroll
    for (int r = 0; r < 4; r++)
        pa[r] = *(const float4*)&A[(size_t)(m0 + am + r * 32) * DIM + ak];
#pragma unroll
    for (int r = 0; r < 4; r++)
        pb[r] = *(const float4*)&W[(size_t)(bk + r * 8) * Nout + n0 + bn];

    float acc[4][4][4];
#pragma unroll
    for (int i = 0; i < 4; i++)
#pragma unroll
        for (int j = 0; j < 4; j++)
#pragma unroll
            for (int r = 0; r < 4; r++) acc[i][j][r] = 0.f;

    for (int k0 = 0; k0 < DIM; k0 += BK) {
        // commit prefetched tile to smem (tf32)
#pragma unroll
        for (int r = 0; r < 4; r++)
            *(uint4*)&As[(am + r * 32) * AS_STR + ak] =
                make_uint4(f2tf(pa[r].x), f2tf(pa[r].y), f2tf(pa[r].z), f2tf(pa[r].w));
#pragma unroll
        for (int r = 0; r < 4; r++)
            *(uint4*)&Bs[(bk + r * 8) * BS_STR + bn] =
                make_uint4(f2tf(pb[r].x), f2tf(pb[r].y), f2tf(pb[r].z), f2tf(pb[r].w));
        __syncthreads();

        if (k0 + BK < DIM) {
#pragma unroll
            for (int r = 0; r < 4; r++)
                pa[r] = *(const float4*)&A[(size_t)(m0 + am + r * 32) * DIM + k0 + BK + ak];
#pragma unroll
            for (int r = 0; r < 4; r++)
                pb[r] = *(const float4*)&W[(size_t)(k0 + BK + bk + r * 8) * Nout + n0 + bn];
        }

#pragma unroll
        for (int kk = 0; kk < 4; kk++) {
            uint32_t bf[4][2];
#pragma unroll
            for (int nt = 0; nt < 4; nt++) {
                const int n = wn * 32 + nt * 8 + g;
                bf[nt][0] = Bs[(kk * 8 + c) * BS_STR + n];
                bf[nt][1] = Bs[(kk * 8 + c + 4) * BS_STR + n];
            }
#pragma unroll
            for (int mt = 0; mt < 4; mt++) {
                const int m = wm * 64 + mt * 16 + g;
                uint32_t af[4];
                af[0] = As[m * AS_STR + kk * 8 + c];
                af[1] = As[(m + 8) * AS_STR + kk * 8 + c];
                af[2] = As[m * AS_STR + kk * 8 + c + 4];
                af[3] = As[(m + 8) * AS_STR + kk * 8 + c + 4];
#pragma unroll
                for (int nt = 0; nt < 4; nt++)
                    mma8(acc[mt][nt], af, bf[nt]);
            }
        }
        __syncthreads();
    }

    // epilogue
#pragma unroll
    for (int mt = 0; mt < 4; mt++) {
#pragma unroll
        for (int rr = 0; rr < 2; rr++) {
            const int m = m0 + wm * 64 + mt * 16 + g + rr * 8;
            const int b = m >> 11;
            const int nrow = m & 2047;
#pragma unroll
            for (int nt = 0; nt < 4; nt++) {
                const int col = n0 + wn * 32 + nt * 8 + 2 * c;
                float v0 = acc[mt][nt][rr * 2 + 0];
                float v1 = acc[mt][nt][rr * 2 + 1];
                if (MODE == 0) {
                    if (col < INNER) {
                        const int h = col >> 6, d = col & 63;
                        *(float2*)&g_K[(((size_t)(b * HEADS + h)) * SEQ + nrow) * DHEAD + d]
                            = make_float2(v0, v1);
                    } else {
                        const int c2 = col - INNER;
                        const int h = c2 >> 6, d = c2 & 63;
                        *(float2*)&g_V[(((size_t)(b * HEADS + h)) * SEQ + nrow) * DHEAD + d]
                            = make_float2(v0, v1);
                    }
                } else if (MODE == 1) {
                    const int h = col >> 6, d = col & 63;
                    *(float2*)&g_Q[(((size_t)(b * HEADS + h)) * SEQ + nrow) * DHEAD + d]
                        = make_float2(v0, v1);
                } else {
                    *(float2*)&C0[(size_t)m * INNER + col]
                        = make_float2(v0 + bias[col], v1 + bias[col + 1]);
                }
            }
        }
    }
}

// ---------------- flash attention (tf32 mma, 32 q-rows/warp) ----------------
// CTA: 256 queries, 8 warps. Key tile KT=64. 1 CTA/SM, grid = 128 CTAs (1 wave).
#define KT 64
#define KS_STR 68        // Ks[key][d]: QK bf bank = 4g+c -> CF
#define VS_STR 72        // Vs[key][d]: PV bf bank = 8c+g -> CF
#define PS_STR 68        // Ps[q][key]: PV af bank = 4g+c -> CF
#define KS_WORDS (KT * KS_STR)          // 4352
#define VS_WORDS (KT * VS_STR)          // 4608
#define PS_WORDS (256 * PS_STR)         // 17408
#define ATTN_SMEM ((KS_WORDS + VS_WORDS + PS_WORDS) * sizeof(uint32_t))  // 105472 B

__global__ void __launch_bounds__(256, 1)
attn_kernel(void)
{
    extern __shared__ uint32_t smw[];
    uint32_t* Ks = smw;
    uint32_t* Vs = Ks + KS_WORDS;
    uint32_t* Ps = Vs + VS_WORDS;

    const int bh = blockIdx.y;
    const int q0 = blockIdx.x * 256;
    const float* Qg = g_Q + (size_t)bh * SEQ * DHEAD;
    const float* Kg = g_K + (size_t)bh * SEQ * DHEAD;
    const float* Vg = g_V + (size_t)bh * SEQ * DHEAD;

    const int tid  = threadIdx.x;
    const int warp = tid >> 5;
    const int lane = tid & 31;
    const int g = lane >> 2;
    const int c = lane & 3;
    const int qb = q0 + warp * 32;       // warp's 32-query block

    // Q fragments (scale * log2e folded in; softmax in base-2)
    const float S2 = SCALE * 1.4426950408889634f;
    uint32_t qa[8][8];
#pragma unroll
    for (int kk = 0; kk < 8; kk++) {
        const int d = kk * 8 + c;
        qa[kk][0] = f2tf(S2 * Qg[(size_t)(qb + g) * DHEAD + d]);
        qa[kk][1] = f2tf(S2 * Qg[(size_t)(qb + g + 8) * DHEAD + d]);
        qa[kk][2] = f2tf(S2 * Qg[(size_t)(qb + g) * DHEAD + d + 4]);
        qa[kk][3] = f2tf(S2 * Qg[(size_t)(qb + g + 8) * DHEAD + d + 4]);
        qa[kk][4] = f2tf(S2 * Qg[(size_t)(qb + g + 16) * DHEAD + d]);
        qa[kk][5] = f2tf(S2 * Qg[(size_t)(qb + g + 24) * DHEAD + d]);
        qa[kk][6] = f2tf(S2 * Qg[(size_t)(qb + g + 16) * DHEAD + d + 4]);
        qa[kk][7] = f2tf(S2 * Qg[(size_t)(qb + g + 24) * DHEAD + d + 4]);
    }

    const float NEG_INF = __int_as_float(0xff800000);
    float m[4], l[4];
#pragma unroll
    for (int i = 0; i < 4; i++) { m[i] = NEG_INF; l[i] = 0.f; }
    float oacc[8][8];
#pragma unroll
    for (int dt = 0; dt < 8; dt++)
#pragma unroll
        for (int r = 0; r < 8; r++) oacc[dt][r] = 0.f;

    const int skey = tid >> 4;           // 0..15 (+16*r)
    const int sd   = (tid & 15) * 4;

    for (int kv0 = 0; kv0 < SEQ; kv0 += KT) {
        // --- stage K,V tiles [64 x 64] as tf32 ---
#pragma unroll
        for (int r = 0; r < 4; r++) {
            const int key = r * 16 + skey;
            float4 kv = *(const float4*)&Kg[(size_t)(kv0 + key) * DHEAD + sd];
            *(uint4*)&Ks[key * KS_STR + sd] =
                make_uint4(f2tf(kv.x), f2tf(kv.y), f2tf(kv.z), f2tf(kv.w));
            float4 vv = *(const float4*)&Vg[(size_t)(kv0 + key) * DHEAD + sd];
            *(uint4*)&Vs[key * VS_STR + sd] =
                make_uint4(f2tf(vv.x), f2tf(vv.y), f2tf(vv.z), f2tf(vv.w));
        }
        __syncthreads();

        // --- S = Q @ K^T : warp covers 32q x 64key ---
        float sacc[8][8];
#pragma unroll
        for (int nt = 0; nt < 8; nt++)
#pragma unroll
            for (int r = 0; r < 8; r++) sacc[nt][r] = 0.f;

#pragma unroll
        for (int kk = 0; kk < 8; kk++) {
#pragma unroll
            for (int nt = 0; nt < 8; nt++) {
                uint32_t bf[2];
                const int key = nt * 8 + g;
                bf[0] = Ks[key * KS_STR + kk * 8 + c];
                bf[1] = Ks[key * KS_STR + kk * 8 + c + 4];
                mma8(&sacc[nt][0], &qa[kk][0], bf);
                mma8(&sacc[nt][4], &qa[kk][4], bf);
            }
        }

        // --- online softmax (base 2), rows g, g+8, g+16, g+24 ---
        float mx[4];
#pragma unroll
        for (int i = 0; i < 4; i++) mx[i] = NEG_INF;
#pragma unroll
        for (int nt = 0; nt < 8; nt++) {
            mx[0] = fmaxf(mx[0], fmaxf(sacc[nt][0], sacc[nt][1]));
            mx[1] = fmaxf(mx[1], fmaxf(sacc[nt][2], sacc[nt][3]));
            mx[2] = fmaxf(mx[2], fmaxf(sacc[nt][4], sacc[nt][5]));
            mx[3] = fmaxf(mx[3], fmaxf(sacc[nt][6], sacc[nt][7]));
        }
        float al[4], rs[4];
#pragma unroll
        for (int i = 0; i < 4; i++) {
            mx[i] = fmaxf(mx[i], __shfl_xor_sync(0xffffffffu, mx[i], 1));
            mx[i] = fmaxf(mx[i], __shfl_xor_sync(0xffffffffu, mx[i], 2));
            const float mn = fmaxf(m[i], mx[i]);
            al[i] = ex2(m[i] - mn);
            m[i] = mn;
            rs[i] = 0.f;
        }
#pragma unroll
        for (int nt = 0; nt < 8; nt++) {
            float p0 = ex2(sacc[nt][0] - m[0]);
            float p1 = ex2(sacc[nt][1] - m[0]);
            float p2 = ex2(sacc[nt][2] - m[1]);
            float p3 = ex2(sacc[nt][3] - m[1]);
            float p4 = ex2(sacc[nt][4] - m[2]);
            float p5 = ex2(sacc[nt][5] - m[2]);
            float p6 = ex2(sacc[nt][6] - m[3]);
            float p7 = ex2(sacc[nt][7] - m[3]);
            sacc[nt][0] = p0; sacc[nt][1] = p1; sacc[nt][2] = p2; sacc[nt][3] = p3;
            sacc[nt][4] = p4; sacc[nt][5] = p5; sacc[nt][6] = p6; sacc[nt][7] = p7;
            rs[0] += p0 + p1; rs[1] += p2 + p3; rs[2] += p4 + p5; rs[3] += p6 + p7;
        }
#pragma unroll
        for (int i = 0; i < 4; i++) {
            rs[i] += __shfl_xor_sync(0xffffffffu, rs[i], 1);
            rs[i] += __shfl_xor_sync(0xffffffffu, rs[i], 2);
            l[i] = l[i] * al[i] + rs[i];
        }
#pragma unroll
        for (int dt = 0; dt < 8; dt++) {
            oacc[dt][0] *= al[0]; oacc[dt][1] *= al[0];
            oacc[dt][2] *= al[1]; oacc[dt][3] *= al[1];
            oacc[dt][4] *= al[2]; oacc[dt][5] *= al[2];
            oacc[dt][6] *= al[3]; oacc[dt][7] *= al[3];
        }

        // --- stage P (warp-private rows) ---
#pragma unroll
        for (int nt = 0; nt < 8; nt++) {
            const int base = nt * 8 + 2 * c;
            *(uint2*)&Ps[(warp * 32 + g) * PS_STR + base] =
                make_uint2(f2tf(sacc[nt][0]), f2tf(sacc[nt][1]));
            *(uint2*)&Ps[(warp * 32 + g + 8) * PS_STR + base] =
                make_uint2(f2tf(sacc[nt][2]), f2tf(sacc[nt][3]));
            *(uint2*)&Ps[(warp * 32 + g + 16) * PS_STR + base] =
                make_uint2(f2tf(sacc[nt][4]), f2tf(sacc[nt][5]));
            *(uint2*)&Ps[(warp * 32 + g + 24) * PS_STR + base] =
                make_uint2(f2tf(sacc[nt][6]), f2tf(sacc[nt][7]));
        }
        __syncwarp();   // cross-lane smem dependency within warp

        // --- O += P @ V ---
#pragma unroll
        for (int kk = 0; kk < 8; kk++) {
            uint32_t af0[4], af1[4];
            const int pr = warp * 32;
            af0[0] = Ps[(pr + g) * PS_STR + kk * 8 + c];
            af0[1] = Ps[(pr + g + 8) * PS_STR + kk * 8 + c];
            af0[2] = Ps[(pr + g) * PS_STR + kk * 8 + c + 4];
            af0[3] = Ps[(pr + g + 8) * PS_STR + kk * 8 + c + 4];
            af1[0] = Ps[(pr + g + 16) * PS_STR + kk * 8 + c];
            af1[1] = Ps[(pr + g + 24) * PS_STR + kk * 8 + c];
            af1[2] = Ps[(pr + g + 16) * PS_STR + kk * 8 + c + 4];
            af1[3] = Ps[(pr + g + 24) * PS_STR + kk * 8 + c + 4];
#pragma unroll
            for (int dt = 0; dt < 8; dt++) {
                uint32_t bf[2];
                bf[0] = Vs[(kk * 8 + c) * VS_STR + dt * 8 + g];
                bf[1] = Vs[(kk * 8 + c + 4) * VS_STR + dt * 8 + g];
                mma8(&oacc[dt][0], af0, bf);
                mma8(&oacc[dt][4], af1, bf);
            }
        }
        __syncthreads();   // before next tile overwrites Ks/Vs
    }

    // --- epilogue: AO[b][n][h*64+d] ---
    const int b = bh >> 3;
    const int h = bh & 7;
    float inv[4];
#pragma unroll
    for (int i = 0; i < 4; i++) inv[i] = 1.f / l[i];
#pragma unroll
    for (int dt = 0; dt < 8; dt++) {
        const int d = dt * 8 + 2 * c;
        *(float2*)&g_AO[((size_t)(b * SEQ + qb + g)) * INNER + h * DHEAD + d] =
            make_float2(oacc[dt][0] * inv[0], oacc[dt][1] * inv[0]);
        *(float2*)&g_AO[((size_t)(b * SEQ + qb + g + 8)) * INNER + h * DHEAD + d] =
            make_float2(oacc[dt][2] * inv[1], oacc[dt][3] * inv[1]);
        *(float2*)&g_AO[((size_t)(b * SEQ + qb + g + 16)) * INNER + h * DHEAD + d] =
            make_float2(oacc[dt][4] * inv[2], oacc[dt][5] * inv[2]);
        *(float2*)&g_AO[((size_t)(b * SEQ + qb + g + 24)) * INNER + h * DHEAD + d] =
            make_float2(oacc[dt][6] * inv[3], oacc[dt][7] * inv[3]);
    }
}

// ---------------- launch ----------------
extern "C" void kernel_launch(void* const* d_in, const int* in_sizes, int n_in,
                              void* d_out, int out_size)
{
    const float* x1    = (const float*)d_in[0];
    const float* x2    = (const float*)d_in[1];
    const float* W_qk  = (const float*)d_in[2];
    const float* W_v   = (const float*)d_in[3];
    const float* W_out = (const float*)d_in[4];
    const float* b_out = (const float*)d_in[5];
    float* out = (float*)d_out;
    (void)in_sizes; (void)n_in; (void)out_size;

    cudaFuncSetAttribute(attn_kernel, cudaFuncAttributeMaxDynamicSharedMemorySize,
                         (int)ATTN_SMEM);

    float* gAO;
    cudaGetSymbolAddress((void**)&gAO, g_AO);

    gemm_kernel<0><<<dim3(2 * INNER / BN, MROWS / BM), 256>>>(x1, W_qk, nullptr, nullptr, 2 * INNER);
    gemm_kernel<1><<<dim3(INNER / BN, MROWS / BM), 256>>>(x2, W_v, nullptr, nullptr, INNER);
    attn_kernel<<<dim3(SEQ / 256, BATCH * HEADS), 256, ATTN_SMEM>>>();
    gemm_kernel<2><<<dim3(DIM / BN, MROWS / BM), 256>>>(gAO, W_out, out, b_out, DIM);
}

// round 4
// speedup vs baseline: 9.6700x; 1.9072x over previous
#include <cuda_runtime.h>
#include <cuda_fp16.h>
#include <cstdint>

// Problem constants
#define BATCH 2
#define SEQ   2048
#define DIM   512
#define HEADS 8
#define DHEAD 64
#define INNER 512
#define MROWS (BATCH * SEQ)
#define SCALE 0.125f

// ---------------- scratch (fp16) ----------------
__device__ __half g_Q[BATCH * HEADS * SEQ * DHEAD];   // [b,h,n,d], pre-scaled by SCALE*log2e
__device__ __half g_K[BATCH * HEADS * SEQ * DHEAD];
__device__ __half g_V[BATCH * HEADS * SEQ * DHEAD];
__device__ __half g_AO[MROWS * INNER];                // [b,n, h*64+d]

// ---------------- helpers ----------------
__device__ __forceinline__ float ex2(float x) {
    float y;
    asm("ex2.approx.f32 %0, %1;" : "=f"(y) : "f"(x));
    return y;
}
__device__ __forceinline__ uint32_t pack2(float a, float b) {
    __half2 h = __floats2half2_rn(a, b);
    return *(uint32_t*)&h;
}
// D += A*B : m16n8k16 fp16 in, fp32 accum
__device__ __forceinline__ void mma16(float* c, const uint32_t* a, const uint32_t* b) {
    asm volatile(
        "mma.sync.aligned.m16n8k16.row.col.f32.f16.f16.f32 "
        "{%0,%1,%2,%3},{%4,%5,%6,%7},{%8,%9},{%0,%1,%2,%3};"
        : "+f"(c[0]), "+f"(c[1]), "+f"(c[2]), "+f"(c[3])
        : "r"(a[0]), "r"(a[1]), "r"(a[2]), "r"(a[3]), "r"(b[0]), "r"(b[1]));
}
__device__ __forceinline__ void ldsm4(uint32_t* r, uint32_t addr) {
    asm volatile("ldmatrix.sync.aligned.m8n8.x4.shared.b16 {%0,%1,%2,%3}, [%4];"
                 : "=r"(r[0]), "=r"(r[1]), "=r"(r[2]), "=r"(r[3]) : "r"(addr));
}
__device__ __forceinline__ void ldsm2(uint32_t* r, uint32_t addr) {
    asm volatile("ldmatrix.sync.aligned.m8n8.x2.shared.b16 {%0,%1}, [%2];"
                 : "=r"(r[0]), "=r"(r[1]) : "r"(addr));
}
__device__ __forceinline__ void ldsm2t(uint32_t* r, uint32_t addr) {
    asm volatile("ldmatrix.sync.aligned.m8n8.x2.trans.shared.b16 {%0,%1}, [%2];"
                 : "=r"(r[0]), "=r"(r[1]) : "r"(addr));
}

// ---------------- GEMM: C = A[M,512] @ W[512,Nout] ----------------
// 128x128 CTA tile, 8 warps each 64m x 32n, fp16 mma + ldmatrix, reg prefetch.
#define BM 128
#define BN 128
#define BK 32
#define AS_STR 40    // halves; 16B-unit stride 5 -> CF
#define BS_STR 136   // halves; 16B-unit stride 17 -> CF

template <int MODE>
__global__ void __launch_bounds__(256)
gemm_kernel(const void* __restrict__ Av,
            const float* __restrict__ W,
            float* __restrict__ C0,
            const float* __restrict__ bias,
            int Nout)
{
    __shared__ __half As[BM * AS_STR];   // 10 KB
    __shared__ __half Bs[BK * BS_STR];   // 8.5 KB

    const int m0 = blockIdx.y * BM;
    const int n0 = blockIdx.x * BN;
    const int tid  = threadIdx.x;
    const int warp = tid >> 5;
    const int lane = tid & 31;
    const int wm = warp >> 2;       // 0..1 : 64 rows
    const int wn = warp & 3;        // 0..3 : 32 cols
    const int g  = lane >> 2;
    const int c  = lane & 3;

    const uint32_t sAs = (uint32_t)__cvta_generic_to_shared(As);
    const uint32_t sBs = (uint32_t)__cvta_generic_to_shared(Bs);

    // staging maps
    const int am_f = tid >> 3;          // fp32 A: rows (+32*r), cols (tid&7)*4
    const int ak_f = (tid & 7) * 4;
    const int am_h = tid >> 1;          // fp16 A: row 0..127, cols (tid&1)*16 (+8)
    const int ak_h = (tid & 1) * 16;
    const int bk = tid >> 5;            // B: rows (+8*r), cols (tid&31)*4
    const int bn = (tid & 31) * 4;

    const float* Af = (const float*)Av;
    const __half* Ah = (const __half*)Av;

    // prefetch k0 = 0
    float4 pa_f[4]; uint4 pa_h[2]; float4 pb[4];
    if (MODE == 2) {
#pragma unroll
        for (int r = 0; r < 2; r++)
            pa_h[r] = *(const uint4*)&Ah[(size_t)(m0 + am_h) * DIM + ak_h + r * 8];
    } else {
#pragma unroll
        for (int r = 0; r < 4; r++)
            pa_f[r] = *(const float4*)&Af[(size_t)(m0 + am_f + r * 32) * DIM + ak_f];
    }
#pragma unroll
    for (int r = 0; r < 4; r++)
        pb[r] = *(const float4*)&W[(size_t)(bk + r * 8) * Nout + n0 + bn];

    float acc[4][4][4];
#pragma unroll
    for (int i = 0; i < 4; i++)
#pragma unroll
        for (int j = 0; j < 4; j++)
#pragma unroll
            for (int r = 0; r < 4; r++) acc[i][j][r] = 0.f;

    for (int k0 = 0; k0 < DIM; k0 += BK) {
        // commit prefetched tile to smem
        if (MODE == 2) {
#pragma unroll
            for (int r = 0; r < 2; r++)
                *(uint4*)&As[am_h * AS_STR + ak_h + r * 8] = pa_h[r];
        } else {
#pragma unroll
            for (int r = 0; r < 4; r++) {
                const int m = am_f + r * 32;
                *(uint2*)&As[m * AS_STR + ak_f] = make_uint2(
                    pack2(pa_f[r].x, pa_f[r].y), pack2(pa_f[r].z, pa_f[r].w));
            }
        }
#pragma unroll
        for (int r = 0; r < 4; r++)
            *(uint2*)&Bs[(bk + r * 8) * BS_STR + bn] = make_uint2(
                pack2(pb[r].x, pb[r].y), pack2(pb[r].z, pb[r].w));
        __syncthreads();

        if (k0 + BK < DIM) {
            if (MODE == 2) {
#pragma unroll
                for (int r = 0; r < 2; r++)
                    pa_h[r] = *(const uint4*)&Ah[(size_t)(m0 + am_h) * DIM + k0 + BK + ak_h + r * 8];
            } else {
#pragma unroll
                for (int r = 0; r < 4; r++)
                    pa_f[r] = *(const float4*)&Af[(size_t)(m0 + am_f + r * 32) * DIM + k0 + BK + ak_f];
            }
#pragma unroll
            for (int r = 0; r < 4; r++)
                pb[r] = *(const float4*)&W[(size_t)(k0 + BK + bk + r * 8) * Nout + n0 + bn];
        }

#pragma unroll
        for (int kk = 0; kk < 2; kk++) {
            uint32_t bf[4][2];
#pragma unroll
            for (int nt = 0; nt < 4; nt++)
                ldsm2t(bf[nt], sBs + ((kk * 16 + (lane & 15)) * BS_STR
                                      + wn * 32 + nt * 8) * 2);
#pragma unroll
            for (int mt = 0; mt < 4; mt++) {
                uint32_t af[4];
                ldsm4(af, sAs + ((wm * 64 + mt * 16 + (lane & 15)) * AS_STR
                                 + kk * 16 + (lane >> 4) * 8) * 2);
#pragma unroll
                for (int nt = 0; nt < 4; nt++)
                    mma16(acc[mt][nt], af, bf[nt]);
            }
        }
        __syncthreads();
    }

    // epilogue
    const float QSC = SCALE * 1.4426950408889634f;   // folded into g_Q
#pragma unroll
    for (int mt = 0; mt < 4; mt++) {
#pragma unroll
        for (int rr = 0; rr < 2; rr++) {
            const int m = m0 + wm * 64 + mt * 16 + g + rr * 8;
            const int b = m >> 11;
            const int nrow = m & 2047;
#pragma unroll
            for (int nt = 0; nt < 4; nt++) {
                const int col = n0 + wn * 32 + nt * 8 + 2 * c;
                float v0 = acc[mt][nt][rr * 2 + 0];
                float v1 = acc[mt][nt][rr * 2 + 1];
                if (MODE == 0) {
                    if (col < INNER) {
                        const int h = col >> 6, d = col & 63;
                        *(uint32_t*)&g_K[(((size_t)(b * HEADS + h)) * SEQ + nrow) * DHEAD + d]
                            = pack2(v0, v1);
                    } else {
                        const int c2 = col - INNER;
                        const int h = c2 >> 6, d = c2 & 63;
                        *(uint32_t*)&g_V[(((size_t)(b * HEADS + h)) * SEQ + nrow) * DHEAD + d]
                            = pack2(v0, v1);
                    }
                } else if (MODE == 1) {
                    const int h = col >> 6, d = col & 63;
                    *(uint32_t*)&g_Q[(((size_t)(b * HEADS + h)) * SEQ + nrow) * DHEAD + d]
                        = pack2(v0 * QSC, v1 * QSC);
                } else {
                    *(float2*)&C0[(size_t)m * INNER + col]
                        = make_float2(v0 + bias[col], v1 + bias[col + 1]);
                }
            }
        }
    }
}

// ---------------- flash attention (fp16 mma, register-resident P) ----------------
// CTA: 256 queries, 8 warps (32 q each). KT=64 keys/tile.
#define KT 64
#define KV_STR 72        // halves; 16B-unit stride 9 -> CF for all ldmatrix patterns

__global__ void __launch_bounds__(256, 1)
attn_kernel(void)
{
    __shared__ __half Ks[KT * KV_STR];   // 9 KB
    __shared__ __half Vs[KT * KV_STR];   // 9 KB

    const int bh = blockIdx.y;
    const int q0 = blockIdx.x * 256;
    const __half* Qg = g_Q + (size_t)bh * SEQ * DHEAD;
    const __half* Kg = g_K + (size_t)bh * SEQ * DHEAD;
    const __half* Vg = g_V + (size_t)bh * SEQ * DHEAD;

    const int tid  = threadIdx.x;
    const int warp = tid >> 5;
    const int lane = tid & 31;
    const int g = lane >> 2;
    const int c = lane & 3;
    const int qb = q0 + warp * 32;

    const uint32_t sKs = (uint32_t)__cvta_generic_to_shared(Ks);
    const uint32_t sVs = (uint32_t)__cvta_generic_to_shared(Vs);

    // --- Q A-fragments straight from gmem (already scaled) ---
    uint32_t qa[4][8];
#pragma unroll
    for (int kk = 0; kk < 4; kk++) {
        const int d = kk * 16 + 2 * c;
        qa[kk][0] = *(const uint32_t*)&Qg[(size_t)(qb + g) * DHEAD + d];
        qa[kk][1] = *(const uint32_t*)&Qg[(size_t)(qb + g + 8) * DHEAD + d];
        qa[kk][2] = *(const uint32_t*)&Qg[(size_t)(qb + g) * DHEAD + d + 8];
        qa[kk][3] = *(const uint32_t*)&Qg[(size_t)(qb + g + 8) * DHEAD + d + 8];
        qa[kk][4] = *(const uint32_t*)&Qg[(size_t)(qb + g + 16) * DHEAD + d];
        qa[kk][5] = *(const uint32_t*)&Qg[(size_t)(qb + g + 24) * DHEAD + d];
        qa[kk][6] = *(const uint32_t*)&Qg[(size_t)(qb + g + 16) * DHEAD + d + 8];
        qa[kk][7] = *(const uint32_t*)&Qg[(size_t)(qb + g + 24) * DHEAD + d + 8];
    }

    const float NEG_INF = __int_as_float(0xff800000);
    float m[4], l[4];
#pragma unroll
    for (int i = 0; i < 4; i++) { m[i] = NEG_INF; l[i] = 0.f; }
    float oacc[8][8];
#pragma unroll
    for (int dt = 0; dt < 8; dt++)
#pragma unroll
        for (int r = 0; r < 8; r++) oacc[dt][r] = 0.f;

    // staging map: key = tid>>2 (0..63), d chunks of 8 at (tid&3)*16
    const int skey = tid >> 2;
    const int sd   = (tid & 3) * 16;

    // prefetch tile 0
    uint4 pk0 = *(const uint4*)&Kg[(size_t)skey * DHEAD + sd];
    uint4 pk1 = *(const uint4*)&Kg[(size_t)skey * DHEAD + sd + 8];
    uint4 pv0 = *(const uint4*)&Vg[(size_t)skey * DHEAD + sd];
    uint4 pv1 = *(const uint4*)&Vg[(size_t)skey * DHEAD + sd + 8];

    for (int kv0 = 0; kv0 < SEQ; kv0 += KT) {
        // commit prefetched K/V to smem
        *(uint4*)&Ks[skey * KV_STR + sd]     = pk0;
        *(uint4*)&Ks[skey * KV_STR + sd + 8] = pk1;
        *(uint4*)&Vs[skey * KV_STR + sd]     = pv0;
        *(uint4*)&Vs[skey * KV_STR + sd + 8] = pv1;
        __syncthreads();

        if (kv0 + KT < SEQ) {
            pk0 = *(const uint4*)&Kg[(size_t)(kv0 + KT + skey) * DHEAD + sd];
            pk1 = *(const uint4*)&Kg[(size_t)(kv0 + KT + skey) * DHEAD + sd + 8];
            pv0 = *(const uint4*)&Vg[(size_t)(kv0 + KT + skey) * DHEAD + sd];
            pv1 = *(const uint4*)&Vg[(size_t)(kv0 + KT + skey) * DHEAD + sd + 8];
        }

        // --- S = Q @ K^T : 32q x 64key per warp ---
        float sacc[8][8];
#pragma unroll
        for (int nt = 0; nt < 8; nt++)
#pragma unroll
            for (int r = 0; r < 8; r++) sacc[nt][r] = 0.f;

#pragma unroll
        for (int kk = 0; kk < 4; kk++) {
#pragma unroll
            for (int nt = 0; nt < 8; nt++) {
                uint32_t bf[2];
                ldsm2(bf, sKs + ((nt * 8 + (lane & 7)) * KV_STR
                                 + kk * 16 + ((lane >> 3) & 1) * 8) * 2);
                mma16(&sacc[nt][0], &qa[kk][0], bf);
                mma16(&sacc[nt][4], &qa[kk][4], bf);
            }
        }

        // --- online softmax (base 2), row groups g,g+8,g+16,g+24 ---
        float mx[4];
#pragma unroll
        for (int i = 0; i < 4; i++) mx[i] = NEG_INF;
#pragma unroll
        for (int nt = 0; nt < 8; nt++) {
            mx[0] = fmaxf(mx[0], fmaxf(sacc[nt][0], sacc[nt][1]));
            mx[1] = fmaxf(mx[1], fmaxf(sacc[nt][2], sacc[nt][3]));
            mx[2] = fmaxf(mx[2], fmaxf(sacc[nt][4], sacc[nt][5]));
            mx[3] = fmaxf(mx[3], fmaxf(sacc[nt][6], sacc[nt][7]));
        }
        float al[4], rs[4];
#pragma unroll
        for (int i = 0; i < 4; i++) {
            mx[i] = fmaxf(mx[i], __shfl_xor_sync(0xffffffffu, mx[i], 1));
            mx[i] = fmaxf(mx[i], __shfl_xor_sync(0xffffffffu, mx[i], 2));
            const float mn = fmaxf(m[i], mx[i]);
            al[i] = ex2(m[i] - mn);
            m[i] = mn;
            rs[i] = 0.f;
        }
#pragma unroll
        for (int nt = 0; nt < 8; nt++) {
            float p0 = ex2(sacc[nt][0] - m[0]);
            float p1 = ex2(sacc[nt][1] - m[0]);
            float p2 = ex2(sacc[nt][2] - m[1]);
            float p3 = ex2(sacc[nt][3] - m[1]);
            float p4 = ex2(sacc[nt][4] - m[2]);
            float p5 = ex2(sacc[nt][5] - m[2]);
            float p6 = ex2(sacc[nt][6] - m[3]);
            float p7 = ex2(sacc[nt][7] - m[3]);
            sacc[nt][0] = p0; sacc[nt][1] = p1; sacc[nt][2] = p2; sacc[nt][3] = p3;
            sacc[nt][4] = p4; sacc[nt][5] = p5; sacc[nt][6] = p6; sacc[nt][7] = p7;
            rs[0] += p0 + p1; rs[1] += p2 + p3; rs[2] += p4 + p5; rs[3] += p6 + p7;
        }
#pragma unroll
        for (int i = 0; i < 4; i++) {
            rs[i] += __shfl_xor_sync(0xffffffffu, rs[i], 1);
            rs[i] += __shfl_xor_sync(0xffffffffu, rs[i], 2);
            l[i] = l[i] * al[i] + rs[i];
        }
#pragma unroll
        for (int dt = 0; dt < 8; dt++) {
            oacc[dt][0] *= al[0]; oacc[dt][1] *= al[0];
            oacc[dt][2] *= al[1]; oacc[dt][3] *= al[1];
            oacc[dt][4] *= al[2]; oacc[dt][5] *= al[2];
            oacc[dt][6] *= al[3]; oacc[dt][7] *= al[3];
        }

        // --- O += P @ V : P packed in registers (S C-frag == PV A-frag layout) ---
#pragma unroll
        for (int kk = 0; kk < 4; kk++) {
            uint32_t pa[8];
            pa[0] = pack2(sacc[2 * kk][0], sacc[2 * kk][1]);
            pa[1] = pack2(sacc[2 * kk][2], sacc[2 * kk][3]);
            pa[2] = pack2(sacc[2 * kk + 1][0], sacc[2 * kk + 1][1]);
            pa[3] = pack2(sacc[2 * kk + 1][2], sacc[2 * kk + 1][3]);
            pa[4] = pack2(sacc[2 * kk][4], sacc[2 * kk][5]);
            pa[5] = pack2(sacc[2 * kk][6], sacc[2 * kk][7]);
            pa[6] = pack2(sacc[2 * kk + 1][4], sacc[2 * kk + 1][5]);
            pa[7] = pack2(sacc[2 * kk + 1][6], sacc[2 * kk + 1][7]);
#pragma unroll
            for (int dt = 0; dt < 8; dt++) {
                uint32_t bf[2];
                ldsm2t(bf, sVs + ((kk * 16 + (lane & 15)) * KV_STR + dt * 8) * 2);
                mma16(&oacc[dt][0], &pa[0], bf);
                mma16(&oacc[dt][4], &pa[4], bf);
            }
        }
        __syncthreads();   // all reads done before next commit
    }

    // --- epilogue: AO[b][n][h*64+d] (fp16) ---
    const int b = bh >> 3;
    const int h = bh & 7;
    float inv[4];
#pragma unroll
    for (int i = 0; i < 4; i++) inv[i] = 1.f / l[i];
#pragma unroll
    for (int dt = 0; dt < 8; dt++) {
        const int d = dt * 8 + 2 * c;
        *(uint32_t*)&g_AO[((size_t)(b * SEQ + qb + g)) * INNER + h * DHEAD + d] =
            pack2(oacc[dt][0] * inv[0], oacc[dt][1] * inv[0]);
        *(uint32_t*)&g_AO[((size_t)(b * SEQ + qb + g + 8)) * INNER + h * DHEAD + d] =
            pack2(oacc[dt][2] * inv[1], oacc[dt][3] * inv[1]);
        *(uint32_t*)&g_AO[((size_t)(b * SEQ + qb + g + 16)) * INNER + h * DHEAD + d] =
            pack2(oacc[dt][4] * inv[2], oacc[dt][5] * inv[2]);
        *(uint32_t*)&g_AO[((size_t)(b * SEQ + qb + g + 24)) * INNER + h * DHEAD + d] =
            pack2(oacc[dt][6] * inv[3], oacc[dt][7] * inv[3]);
    }
}

// ---------------- launch ----------------
extern "C" void kernel_launch(void* const* d_in, const int* in_sizes, int n_in,
                              void* d_out, int out_size)
{
    const float* x1    = (const float*)d_in[0];
    const float* x2    = (const float*)d_in[1];
    const float* W_qk  = (const float*)d_in[2];
    const float* W_v   = (const float*)d_in[3];
    const float* W_out = (const float*)d_in[4];
    const float* b_out = (const float*)d_in[5];
    float* out = (float*)d_out;
    (void)in_sizes; (void)n_in; (void)out_size;

    __half* gAO;
    cudaGetSymbolAddress((void**)&gAO, g_AO);

    gemm_kernel<0><<<dim3(2 * INNER / BN, MROWS / BM), 256>>>(x1, W_qk, nullptr, nullptr, 2 * INNER);
    gemm_kernel<1><<<dim3(INNER / BN, MROWS / BM), 256>>>(x2, W_v, nullptr, nullptr, INNER);
    attn_kernel<<<dim3(SEQ / 256, BATCH * HEADS), 256>>>();
    gemm_kernel<2><<<dim3(DIM / BN, MROWS / BM), 256>>>(gAO, W_out, out, b_out, DIM);
}